// round 15
// baseline (speedup 1.0000x reference)
#include <cuda_runtime.h>
#include <cuda_fp16.h>
#include <cstdint>

#define EMB   64
#define NMAX  300000
#define EIMAX 2200000
#define TB    256

// ---------------- scratch (__device__ globals; allocation-free rule) --------
__device__ int   g_deg  [NMAX];
__device__ float g_dinv [NMAX];
__device__ int   g_loc  [NMAX];
__device__ int   g_bsum [2048];
__device__ int   g_bbase[2048];
__device__ int2  g_rng  [NMAX];                 // users: {start,end} in col[]; items: {start,cursor}
__device__ int2  g_adji [EIMAX];                // item rows: {user col, bits(dinv[u])}
__device__ __align__(128) uint4 g_h0[(size_t)NMAX * 8];   // x0 fp16 (8 halves/uint4)
__device__ __align__(128) uint4 g_h1[(size_t)NMAX * 8];   // x1 fp16
__device__ __align__(128) uint4 g_h2[(size_t)NMAX * 8];   // x2 fp16

// ---------------------------------------------------------------------------
__device__ __forceinline__ float4 h2x2_to_f4(unsigned lo, unsigned hi) {
    __half2 a = *(__half2*)&lo;
    __half2 b = *(__half2*)&hi;
    float2 fa = __half22float2(a), fb = __half22float2(b);
    return make_float4(fa.x, fa.y, fb.x, fb.y);
}
__device__ __forceinline__ void f8_to_h8(uint4& out, float4 a, float4 b) {
    __half2 p0 = __floats2half2_rn(a.x, a.y);
    __half2 p1 = __floats2half2_rn(a.z, a.w);
    __half2 p2 = __floats2half2_rn(b.x, b.y);
    __half2 p3 = __floats2half2_rn(b.z, b.w);
    out.x = *(unsigned*)&p0; out.y = *(unsigned*)&p1;
    out.z = *(unsigned*)&p2; out.w = *(unsigned*)&p3;
}

// accumulate w * h8(v) into (sa, sb) — function, not macro (hygiene)
__device__ __forceinline__ void acc8(float4& sa, float4& sb, float wt, uint4 v) {
    float4 fa = h2x2_to_f4(v.x, v.y);
    float4 fb = h2x2_to_f4(v.z, v.w);
    sa.x += wt * fa.x; sa.y += wt * fa.y; sa.z += wt * fa.z; sa.w += wt * fa.w;
    sb.x += wt * fb.x; sb.y += wt * fb.y; sb.z += wt * fb.z; sb.w += wt * fb.w;
}

// ---------------------------------------------------------------------------
__global__ void k_zero_deg(int n) {
    int i = blockIdx.x * blockDim.x + threadIdx.x;
    if (i < n) g_deg[i] = 0;
}

__global__ void k_count_sym(const int* __restrict__ row,
                            const int* __restrict__ col, int Eh) {
    int i = blockIdx.x * blockDim.x + threadIdx.x;
    if (i >= Eh) return;
    atomicAdd(&g_deg[__ldg(row + i)], 1);
    atomicAdd(&g_deg[__ldg(col + i)], 1);
}

__global__ void k_scan_local(int n) {
    __shared__ int sh[TB];
    int i = blockIdx.x * TB + threadIdx.x;
    int v = (i < n) ? g_deg[i] : 0;
    sh[threadIdx.x] = v; __syncthreads();
    #pragma unroll
    for (int ofs = 1; ofs < TB; ofs <<= 1) {
        int t = (threadIdx.x >= ofs) ? sh[threadIdx.x - ofs] : 0;
        __syncthreads();
        sh[threadIdx.x] += t;
        __syncthreads();
    }
    if (i < n) g_loc[i] = sh[threadIdx.x] - v;
    if (threadIdx.x == TB - 1) g_bsum[blockIdx.x] = sh[TB - 1];
}

__global__ void k_scan_bsum(int nb) {
    __shared__ int sh[1024];
    int tid = threadIdx.x;
    int c0 = tid * 2, c1 = tid * 2 + 1;
    int a = (c0 < nb) ? g_bsum[c0] : 0;
    int b = (c1 < nb) ? g_bsum[c1] : 0;
    int tot = a + b;
    sh[tid] = tot; __syncthreads();
    #pragma unroll
    for (int ofs = 1; ofs < 1024; ofs <<= 1) {
        int t = (tid >= ofs) ? sh[tid - ofs] : 0;
        __syncthreads();
        sh[tid] += t;
        __syncthreads();
    }
    int base = sh[tid] - tot;
    if (c0 < nb) g_bbase[c0] = base;
    if (c1 < nb) g_bbase[c1] = base + a;
}

// users (i<U): offsets in input col[]; items: cursor into g_adji at o-Eh
__global__ void k_scan_add(int n, int U, int Eh) {
    int i = blockIdx.x * TB + threadIdx.x;
    if (i >= n) return;
    int o = g_loc[i] + g_bbase[blockIdx.x];
    int dg = g_deg[i];
    if (i < U) g_rng[i] = make_int2(o, o + dg);
    else       g_rng[i] = make_int2(o - Eh, o - Eh);
    g_dinv[i] = rsqrtf((float)(dg + 1));   // +1 self loop
}

// item rows only: 1 atomic + 1 int2 store per interaction
__global__ void k_fill_item(const int* __restrict__ row,
                            const int* __restrict__ col, int Eh) {
    int i = blockIdx.x * blockDim.x + threadIdx.x;
    if (i >= Eh) return;
    int u = __ldg(row + i);
    int v = __ldg(col + i);
    float du = __ldg(&g_dinv[u]);
    int pv = atomicAdd(&g_rng[v].y, 1);
    g_adji[pv] = make_int2(u, __float_as_int(du));
}

// emb (fp32) -> x0 (fp16): one thread per uint4 chunk (8 halves)
__global__ void k_prep(const float* __restrict__ ue,
                       const float* __restrict__ ie,
                       int U, int N) {
    int i = blockIdx.x * blockDim.x + threadIdx.x;
    int total = N * 8;
    if (i >= total) return;
    int node = i >> 3;
    int c = i & 7;
    const float4* p = (node < U)
        ? (const float4*)ue + (size_t)node * 16
        : (const float4*)ie + (size_t)(node - U) * 16;
    float4 a = __ldg(p + 2 * c);
    float4 b = __ldg(p + 2 * c + 1);
    uint4 h; f8_to_h8(h, a, b);
    g_h0[i] = h;
}

// ---------------------------------------------------------------------------
// Fused layer: 8 threads per node, thread c owns halves [8c, 8c+8) (one uint4).
// User rows: adjacency = input col stream, weight = d*dinv[col] (table).
// Item rows: adjacency = int2 {col, weight} inline.
template<bool LAST>
__global__ void __launch_bounds__(TB)
k_layer(const uint4* __restrict__ x,
        uint4* __restrict__ xn,
        const int* __restrict__ gcol,
        const float* __restrict__ ue,
        const float* __restrict__ ie,
        int U,
        float* __restrict__ acc,
        int N) {
    int t = blockIdx.x * blockDim.x + threadIdx.x;
    int node = t >> 3;
    if (node >= N) return;
    int c = t & 7;

    float d = __ldg(&g_dinv[node]);
    int2 rng = __ldg(&g_rng[node]);
    int e = rng.x, end = rng.y;

    size_t idx = (size_t)node * 8 + c;
    uint4 xsh = __ldg(x + idx);
    float4 xsa = h2x2_to_f4(xsh.x, xsh.y);
    float4 xsb = h2x2_to_f4(xsh.z, xsh.w);
    float sw = d * d;
    float4 s0a = make_float4(sw * xsa.x, sw * xsa.y, sw * xsa.z, sw * xsa.w);
    float4 s0b = make_float4(sw * xsb.x, sw * xsb.y, sw * xsb.z, sw * xsb.w);
    float4 s1a = make_float4(0.f, 0.f, 0.f, 0.f);
    float4 s1b = make_float4(0.f, 0.f, 0.f, 0.f);

    if (node < U) {
        while (e + 4 <= end) {
            int c0 = __ldg(gcol + e);
            int c1 = __ldg(gcol + e + 1);
            int c2 = __ldg(gcol + e + 2);
            int c3 = __ldg(gcol + e + 3);
            uint4 v0 = __ldg(x + (size_t)c0 * 8 + c);
            uint4 v1 = __ldg(x + (size_t)c1 * 8 + c);
            uint4 v2 = __ldg(x + (size_t)c2 * 8 + c);
            uint4 v3 = __ldg(x + (size_t)c3 * 8 + c);
            float w0 = d * __ldg(&g_dinv[c0]);
            float w1 = d * __ldg(&g_dinv[c1]);
            float w2 = d * __ldg(&g_dinv[c2]);
            float w3 = d * __ldg(&g_dinv[c3]);
            acc8(s0a, s0b, w0, v0);
            acc8(s1a, s1b, w1, v1);
            acc8(s0a, s0b, w2, v2);
            acc8(s1a, s1b, w3, v3);
            e += 4;
        }
        if (e + 2 <= end) {
            int c0 = __ldg(gcol + e);
            int c1 = __ldg(gcol + e + 1);
            uint4 v0 = __ldg(x + (size_t)c0 * 8 + c);
            uint4 v1 = __ldg(x + (size_t)c1 * 8 + c);
            float w0 = d * __ldg(&g_dinv[c0]);
            float w1 = d * __ldg(&g_dinv[c1]);
            acc8(s0a, s0b, w0, v0);
            acc8(s1a, s1b, w1, v1);
            e += 2;
        }
        if (e < end) {
            int c0 = __ldg(gcol + e);
            uint4 v0 = __ldg(x + (size_t)c0 * 8 + c);
            float w0 = d * __ldg(&g_dinv[c0]);
            acc8(s0a, s0b, w0, v0);
        }
    } else {
        while (e + 4 <= end) {
            int2 a0 = __ldg(&g_adji[e]);
            int2 a1 = __ldg(&g_adji[e + 1]);
            int2 a2 = __ldg(&g_adji[e + 2]);
            int2 a3 = __ldg(&g_adji[e + 3]);
            uint4 v0 = __ldg(x + (size_t)a0.x * 8 + c);
            uint4 v1 = __ldg(x + (size_t)a1.x * 8 + c);
            uint4 v2 = __ldg(x + (size_t)a2.x * 8 + c);
            uint4 v3 = __ldg(x + (size_t)a3.x * 8 + c);
            float w0 = d * __int_as_float(a0.y);
            float w1 = d * __int_as_float(a1.y);
            float w2 = d * __int_as_float(a2.y);
            float w3 = d * __int_as_float(a3.y);
            acc8(s0a, s0b, w0, v0);
            acc8(s1a, s1b, w1, v1);
            acc8(s0a, s0b, w2, v2);
            acc8(s1a, s1b, w3, v3);
            e += 4;
        }
        if (e + 2 <= end) {
            int2 a0 = __ldg(&g_adji[e]);
            int2 a1 = __ldg(&g_adji[e + 1]);
            uint4 v0 = __ldg(x + (size_t)a0.x * 8 + c);
            uint4 v1 = __ldg(x + (size_t)a1.x * 8 + c);
            float w0 = d * __int_as_float(a0.y);
            float w1 = d * __int_as_float(a1.y);
            acc8(s0a, s0b, w0, v0);
            acc8(s1a, s1b, w1, v1);
            e += 2;
        }
        if (e < end) {
            int2 a0 = __ldg(&g_adji[e]);
            uint4 v0 = __ldg(x + (size_t)a0.x * 8 + c);
            float w0 = d * __int_as_float(a0.y);
            acc8(s0a, s0b, w0, v0);
        }
    }
    float4 sa = make_float4(s0a.x + s1a.x, s0a.y + s1a.y, s0a.z + s1a.z, s0a.w + s1a.w);
    float4 sb = make_float4(s0b.x + s1b.x, s0b.y + s1b.y, s0b.z + s1b.z, s0b.w + s1b.w);

    if (!LAST) {
        uint4 h; f8_to_h8(h, sa, sb);
        xn[idx] = h;
    } else {
        const float4* pe = (node < U)
            ? (const float4*)ue + (size_t)node * 16
            : (const float4*)ie + (size_t)(node - U) * 16;
        float4 ea = __ldg(pe + 2 * c);
        float4 eb = __ldg(pe + 2 * c + 1);
        uint4 h1 = __ldg(&g_h1[idx]);
        float4 v1a = h2x2_to_f4(h1.x, h1.y);
        float4 v1b = h2x2_to_f4(h1.z, h1.w);
        ea.x += v1a.x + xsa.x + sa.x;
        ea.y += v1a.y + xsa.y + sa.y;
        ea.z += v1a.z + xsa.z + sa.z;
        ea.w += v1a.w + xsa.w + sa.w;
        eb.x += v1b.x + xsb.x + sb.x;
        eb.y += v1b.y + xsb.y + sb.y;
        eb.z += v1b.z + xsb.z + sb.z;
        eb.w += v1b.w + xsb.w + sb.w;
        __stcs((float4*)acc + (size_t)node * 16 + 2 * c,     ea);
        __stcs((float4*)acc + (size_t)node * 16 + 2 * c + 1, eb);
    }
}

// ---------------------------------------------------------------------------
extern "C" void kernel_launch(void* const* d_in, const int* in_sizes, int n_in,
                              void* d_out, int out_size) {
    const int*   edge = (const int*)d_in[0];
    const float* uemb = (const float*)d_in[1];
    const float* iemb = (const float*)d_in[2];

    int E = in_sizes[0] / 2;       // total directed edges
    int Eh = E / 2;                // unique interactions (mirrored halves)
    int U = in_sizes[1] / EMB;
    int I = in_sizes[2] / EMB;
    int N = U + I;

    const int* row = edge;         // first Eh: user ids (sorted ascending)
    const int* col = edge + E;     // first Eh: item ids (grouped per user)
    float* acc = (float*)d_out;

    uint4* h0; cudaGetSymbolAddress((void**)&h0, g_h0);
    uint4* h1; cudaGetSymbolAddress((void**)&h1, g_h1);
    uint4* h2; cudaGetSymbolAddress((void**)&h2, g_h2);

    int NB  = (N + TB - 1) / TB;
    int EBh = (Eh + TB - 1) / TB;

    k_zero_deg  <<<NB, TB>>>(N);
    k_count_sym <<<EBh, TB>>>(row, col, Eh);
    k_scan_local<<<NB, TB>>>(N);
    k_scan_bsum <<<1, 1024>>>(NB);
    k_scan_add  <<<NB, TB>>>(N, U, Eh);
    k_fill_item <<<EBh, TB>>>(row, col, Eh);

    int pblocks = (N * 8 + TB - 1) / TB;
    k_prep<<<pblocks, TB>>>(uemb, iemb, U, N);

    int lblocks = (N * 8 + TB - 1) / TB;          // 8 threads per node
    k_layer<false><<<lblocks, TB>>>(h0, h1, col, uemb, iemb, U, acc, N);
    k_layer<false><<<lblocks, TB>>>(h1, h2, col, uemb, iemb, U, acc, N);
    k_layer<true ><<<lblocks, TB>>>(h2, nullptr, col, uemb, iemb, U, acc, N);
}

// round 16
// speedup vs baseline: 1.3588x; 1.3588x over previous
#include <cuda_runtime.h>
#include <cuda_fp16.h>
#include <cstdint>

#define EMB   64
#define NMAX  300000
#define EMAX  4200000
#define TB    256

// ---------------- scratch (__device__ globals; allocation-free rule) --------
__device__ int   g_deg  [NMAX];
__device__ float g_dinv [NMAX];
__device__ int   g_loc  [NMAX];
__device__ int   g_bsum [2048];
__device__ int   g_bbase[2048];
__device__ int2  g_rng  [NMAX];               // {row_start, end/cursor} into g_adj
__device__ int2  g_adj  [EMAX];               // {col, bits(dinv[col])}; users [0,Eh), items [Eh,2Eh)
__device__ uint2 g_h0[(size_t)NMAX * 16];     // x0 fp16 (4 halves per uint2)
__device__ uint2 g_h1[(size_t)NMAX * 16];     // x1 fp16
__device__ uint2 g_h2[(size_t)NMAX * 16];     // x2 fp16

// ---------------------------------------------------------------------------
__device__ __forceinline__ float4 h4_to_f4(uint2 h) {
    __half2 a = *(__half2*)&h.x;
    __half2 b = *(__half2*)&h.y;
    float2 fa = __half22float2(a), fb = __half22float2(b);
    return make_float4(fa.x, fa.y, fb.x, fb.y);
}
__device__ __forceinline__ uint2 f4_to_h4(float4 v) {
    __half2 a = __floats2half2_rn(v.x, v.y);
    __half2 b = __floats2half2_rn(v.z, v.w);
    uint2 r;
    r.x = *(unsigned*)&a;
    r.y = *(unsigned*)&b;
    return r;
}

// ---------------------------------------------------------------------------
__global__ void k_zero_deg(int n) {
    int i = blockIdx.x * blockDim.x + threadIdx.x;
    if (i < n) g_deg[i] = 0;
}

__global__ void k_count_sym(const int* __restrict__ row,
                            const int* __restrict__ col, int Eh) {
    int i = blockIdx.x * blockDim.x + threadIdx.x;
    if (i >= Eh) return;
    atomicAdd(&g_deg[__ldg(row + i)], 1);
    atomicAdd(&g_deg[__ldg(col + i)], 1);
}

__global__ void k_scan_local(int n) {
    __shared__ int sh[TB];
    int i = blockIdx.x * TB + threadIdx.x;
    int v = (i < n) ? g_deg[i] : 0;
    sh[threadIdx.x] = v; __syncthreads();
    #pragma unroll
    for (int ofs = 1; ofs < TB; ofs <<= 1) {
        int t = (threadIdx.x >= ofs) ? sh[threadIdx.x - ofs] : 0;
        __syncthreads();
        sh[threadIdx.x] += t;
        __syncthreads();
    }
    if (i < n) g_loc[i] = sh[threadIdx.x] - v;
    if (threadIdx.x == TB - 1) g_bsum[blockIdx.x] = sh[TB - 1];
}

__global__ void k_scan_bsum(int nb) {
    __shared__ int sh[1024];
    int tid = threadIdx.x;
    int c0 = tid * 2, c1 = tid * 2 + 1;
    int a = (c0 < nb) ? g_bsum[c0] : 0;
    int b = (c1 < nb) ? g_bsum[c1] : 0;
    int tot = a + b;
    sh[tid] = tot; __syncthreads();
    #pragma unroll
    for (int ofs = 1; ofs < 1024; ofs <<= 1) {
        int t = (tid >= ofs) ? sh[tid - ofs] : 0;
        __syncthreads();
        sh[tid] += t;
        __syncthreads();
    }
    int base = sh[tid] - tot;
    if (c0 < nb) g_bbase[c0] = base;
    if (c1 < nb) g_bbase[c1] = base + a;
}

// users (i<U): {o, o+deg} — o equals the row's start index in input col[]
// items: {o, o} cursor for atomic fill (region [Eh, 2Eh))
__global__ void k_scan_add(int n, int U) {
    int i = blockIdx.x * TB + threadIdx.x;
    if (i >= n) return;
    int o = g_loc[i] + g_bbase[blockIdx.x];
    int dg = g_deg[i];
    if (i < U) g_rng[i] = make_int2(o, o + dg);
    else       g_rng[i] = make_int2(o, o);
    g_dinv[i] = rsqrtf((float)(dg + 1));   // +1 self loop
}

// user half: sequential, atomic-free (user rows in input order occupy [0,Eh))
__global__ void k_fill_user(const int* __restrict__ col, int Eh) {
    int i = blockIdx.x * blockDim.x + threadIdx.x;
    if (i >= Eh) return;
    int v = __ldg(col + i);
    g_adj[i] = make_int2(v, __float_as_int(__ldg(&g_dinv[v])));
}

// item half: cursor fill (1 atomic + 1 int2 store per interaction)
__global__ void k_fill_item(const int* __restrict__ row,
                            const int* __restrict__ col, int Eh) {
    int i = blockIdx.x * blockDim.x + threadIdx.x;
    if (i >= Eh) return;
    int u = __ldg(row + i);
    int v = __ldg(col + i);
    float du = __ldg(&g_dinv[u]);
    int pv = atomicAdd(&g_rng[v].y, 1);
    g_adj[pv] = make_int2(u, __float_as_int(du));
}

// emb (fp32) -> x0 (fp16)
__global__ void k_prep(const float* __restrict__ ue,
                       const float* __restrict__ ie,
                       int U, int N) {
    int i = blockIdx.x * blockDim.x + threadIdx.x;
    int total = N * 16;
    if (i >= total) return;
    int node = i >> 4;
    int c = i & 15;
    const float4* p = (node < U)
        ? (const float4*)ue + (size_t)node * 16
        : (const float4*)ie + (size_t)(node - U) * 16;
    g_h0[i] = f4_to_h4(__ldg(p + c));
}

// ---------------------------------------------------------------------------
// Unified fused layer: 16 threads per node, thread c owns halves [4c,4c+4).
// Adjacency = int2 {col, w} for ALL rows -> 8 warp-LDGs per 8 edges.
// LAST: acc = emb + x1 + x2(self) + x3
template<bool LAST>
__global__ void __launch_bounds__(TB)
k_layer(const uint2* __restrict__ x,
        uint2* __restrict__ xn,
        const float* __restrict__ ue,
        const float* __restrict__ ie,
        int U,
        float* __restrict__ acc,
        int N) {
    int t = blockIdx.x * blockDim.x + threadIdx.x;
    int node = t >> 4;
    if (node >= N) return;
    int c = t & 15;

    float d = __ldg(&g_dinv[node]);
    int2 rng = __ldg(&g_rng[node]);
    int e = rng.x, end = rng.y;

    size_t idx = (size_t)node * 16 + c;
    float4 xs = h4_to_f4(__ldg(x + idx));
    float sw = d * d;
    float4 s0 = make_float4(sw * xs.x, sw * xs.y, sw * xs.z, sw * xs.w);
    float4 s1 = make_float4(0.f, 0.f, 0.f, 0.f);

    while (e + 4 <= end) {
        int2 a0 = __ldg(&g_adj[e]);
        int2 a1 = __ldg(&g_adj[e + 1]);
        int2 a2 = __ldg(&g_adj[e + 2]);
        int2 a3 = __ldg(&g_adj[e + 3]);
        float4 v0 = h4_to_f4(__ldg(x + (size_t)a0.x * 16 + c));
        float4 v1 = h4_to_f4(__ldg(x + (size_t)a1.x * 16 + c));
        float4 v2 = h4_to_f4(__ldg(x + (size_t)a2.x * 16 + c));
        float4 v3 = h4_to_f4(__ldg(x + (size_t)a3.x * 16 + c));
        float w0 = d * __int_as_float(a0.y);
        float w1 = d * __int_as_float(a1.y);
        float w2 = d * __int_as_float(a2.y);
        float w3 = d * __int_as_float(a3.y);
        s0.x += w0 * v0.x + w2 * v2.x;  s1.x += w1 * v1.x + w3 * v3.x;
        s0.y += w0 * v0.y + w2 * v2.y;  s1.y += w1 * v1.y + w3 * v3.y;
        s0.z += w0 * v0.z + w2 * v2.z;  s1.z += w1 * v1.z + w3 * v3.z;
        s0.w += w0 * v0.w + w2 * v2.w;  s1.w += w1 * v1.w + w3 * v3.w;
        e += 4;
    }
    if (e + 2 <= end) {
        int2 a0 = __ldg(&g_adj[e]);
        int2 a1 = __ldg(&g_adj[e + 1]);
        float4 v0 = h4_to_f4(__ldg(x + (size_t)a0.x * 16 + c));
        float4 v1 = h4_to_f4(__ldg(x + (size_t)a1.x * 16 + c));
        float w0 = d * __int_as_float(a0.y);
        float w1 = d * __int_as_float(a1.y);
        s0.x += w0 * v0.x; s0.y += w0 * v0.y; s0.z += w0 * v0.z; s0.w += w0 * v0.w;
        s1.x += w1 * v1.x; s1.y += w1 * v1.y; s1.z += w1 * v1.z; s1.w += w1 * v1.w;
        e += 2;
    }
    if (e < end) {
        int2 a0 = __ldg(&g_adj[e]);
        float4 v0 = h4_to_f4(__ldg(x + (size_t)a0.x * 16 + c));
        float w0 = d * __int_as_float(a0.y);
        s0.x += w0 * v0.x; s0.y += w0 * v0.y; s0.z += w0 * v0.z; s0.w += w0 * v0.w;
    }
    float4 s = make_float4(s0.x + s1.x, s0.y + s1.y, s0.z + s1.z, s0.w + s1.w);

    if (!LAST) {
        xn[idx] = f4_to_h4(s);
    } else {
        const float4* pe = (node < U)
            ? (const float4*)ue + (size_t)node * 16
            : (const float4*)ie + (size_t)(node - U) * 16;
        float4 a  = __ldg(pe + c);
        float4 v1 = h4_to_f4(__ldg(&g_h1[idx]));
        a.x += v1.x + xs.x + s.x;
        a.y += v1.y + xs.y + s.y;
        a.z += v1.z + xs.z + s.z;
        a.w += v1.w + xs.w + s.w;
        __stcs((float4*)acc + idx, a);   // write-once output: evict-first
    }
}

// ---------------------------------------------------------------------------
extern "C" void kernel_launch(void* const* d_in, const int* in_sizes, int n_in,
                              void* d_out, int out_size) {
    const int*   edge = (const int*)d_in[0];
    const float* uemb = (const float*)d_in[1];
    const float* iemb = (const float*)d_in[2];

    int E = in_sizes[0] / 2;       // total directed edges
    int Eh = E / 2;                // unique interactions (mirrored halves)
    int U = in_sizes[1] / EMB;
    int I = in_sizes[2] / EMB;
    int N = U + I;

    const int* row = edge;         // first Eh: user ids (sorted ascending)
    const int* col = edge + E;     // first Eh: item ids (grouped per user)
    float* acc = (float*)d_out;

    uint2* h0; cudaGetSymbolAddress((void**)&h0, g_h0);
    uint2* h1; cudaGetSymbolAddress((void**)&h1, g_h1);
    uint2* h2; cudaGetSymbolAddress((void**)&h2, g_h2);

    int NB  = (N + TB - 1) / TB;
    int EBh = (Eh + TB - 1) / TB;

    k_zero_deg  <<<NB, TB>>>(N);
    k_count_sym <<<EBh, TB>>>(row, col, Eh);
    k_scan_local<<<NB, TB>>>(N);
    k_scan_bsum <<<1, 1024>>>(NB);
    k_scan_add  <<<NB, TB>>>(N, U);
    k_fill_user <<<EBh, TB>>>(col, Eh);
    k_fill_item <<<EBh, TB>>>(row, col, Eh);

    int pblocks = (N * 16 + TB - 1) / TB;
    k_prep<<<pblocks, TB>>>(uemb, iemb, U, N);

    int lblocks = (N * 16 + TB - 1) / TB;        // half-warp per node
    k_layer<false><<<lblocks, TB>>>(h0, h1, uemb, iemb, U, acc, N);
    k_layer<false><<<lblocks, TB>>>(h1, h2, uemb, iemb, U, acc, N);
    k_layer<true ><<<lblocks, TB>>>(h2, nullptr, uemb, iemb, U, acc, N);
}

// round 17
// speedup vs baseline: 1.3691x; 1.0075x over previous
#include <cuda_runtime.h>
#include <cuda_fp16.h>
#include <cstdint>

#define EMB   64
#define NMAX  300000
#define EIMAX 2200000   // item-side adjacency (one entry per interaction)
#define TB    256

// ---------------- scratch (__device__ globals; allocation-free rule) --------
__device__ int   g_deg  [NMAX];
__device__ float g_dinv [NMAX];
__device__ int   g_loc  [NMAX];
__device__ int   g_bsum [2048];
__device__ int   g_bbase[2048];
__device__ int2  g_rng  [NMAX];               // users: {start,end} in col[]; items: {start,cursor} in g_adji
__device__ int2  g_adji [EIMAX];              // item rows: {user col, bits(dinv[u])}
__device__ uint2 g_h0[(size_t)NMAX * 16];     // x0 fp16
__device__ uint2 g_h1[(size_t)NMAX * 16];     // x1 fp16
__device__ uint2 g_h2[(size_t)NMAX * 16];     // x2 fp16

// ---------------------------------------------------------------------------
__device__ __forceinline__ float4 h4_to_f4(uint2 h) {
    __half2 a = *(__half2*)&h.x;
    __half2 b = *(__half2*)&h.y;
    float2 fa = __half22float2(a), fb = __half22float2(b);
    return make_float4(fa.x, fa.y, fb.x, fb.y);
}
__device__ __forceinline__ uint2 f4_to_h4(float4 v) {
    __half2 a = __floats2half2_rn(v.x, v.y);
    __half2 b = __floats2half2_rn(v.z, v.w);
    uint2 r;
    r.x = *(unsigned*)&a;
    r.y = *(unsigned*)&b;
    return r;
}

// ---------------------------------------------------------------------------
__global__ void k_zero_deg(int n) {
    int i = blockIdx.x * blockDim.x + threadIdx.x;
    if (i < n) g_deg[i] = 0;
}

__global__ void k_count_sym(const int* __restrict__ row,
                            const int* __restrict__ col, int Eh) {
    int i = blockIdx.x * blockDim.x + threadIdx.x;
    if (i >= Eh) return;
    atomicAdd(&g_deg[__ldg(row + i)], 1);
    atomicAdd(&g_deg[__ldg(col + i)], 1);
}

__global__ void k_scan_local(int n) {
    __shared__ int sh[TB];
    int i = blockIdx.x * TB + threadIdx.x;
    int v = (i < n) ? g_deg[i] : 0;
    sh[threadIdx.x] = v; __syncthreads();
    #pragma unroll
    for (int ofs = 1; ofs < TB; ofs <<= 1) {
        int t = (threadIdx.x >= ofs) ? sh[threadIdx.x - ofs] : 0;
        __syncthreads();
        sh[threadIdx.x] += t;
        __syncthreads();
    }
    if (i < n) g_loc[i] = sh[threadIdx.x] - v;
    if (threadIdx.x == TB - 1) g_bsum[blockIdx.x] = sh[TB - 1];
}

__global__ void k_scan_bsum(int nb) {
    __shared__ int sh[1024];
    int tid = threadIdx.x;
    int c0 = tid * 2, c1 = tid * 2 + 1;
    int a = (c0 < nb) ? g_bsum[c0] : 0;
    int b = (c1 < nb) ? g_bsum[c1] : 0;
    int tot = a + b;
    sh[tid] = tot; __syncthreads();
    #pragma unroll
    for (int ofs = 1; ofs < 1024; ofs <<= 1) {
        int t = (tid >= ofs) ? sh[tid - ofs] : 0;
        __syncthreads();
        sh[tid] += t;
        __syncthreads();
    }
    int base = sh[tid] - tot;
    if (c0 < nb) g_bbase[c0] = base;
    if (c1 < nb) g_bbase[c1] = base + a;
}

// users (i<U): offsets in input col[]; items: cursor into g_adji at o-Eh
__global__ void k_scan_add(int n, int U, int Eh) {
    int i = blockIdx.x * TB + threadIdx.x;
    if (i >= n) return;
    int o = g_loc[i] + g_bbase[blockIdx.x];
    int dg = g_deg[i];
    if (i < U) g_rng[i] = make_int2(o, o + dg);
    else       g_rng[i] = make_int2(o - Eh, o - Eh);
    g_dinv[i] = rsqrtf((float)(dg + 1));   // +1 self loop
}

// item rows only: 1 atomic + 1 int2 store per interaction
__global__ void k_fill_item(const int* __restrict__ row,
                            const int* __restrict__ col, int Eh) {
    int i = blockIdx.x * blockDim.x + threadIdx.x;
    if (i >= Eh) return;
    int u = __ldg(row + i);
    int v = __ldg(col + i);
    float du = __ldg(&g_dinv[u]);
    int pv = atomicAdd(&g_rng[v].y, 1);
    g_adji[pv] = make_int2(u, __float_as_int(du));
}

// emb (fp32) -> x0 (fp16)
__global__ void k_prep(const float* __restrict__ ue,
                       const float* __restrict__ ie,
                       int U, int N) {
    int i = blockIdx.x * blockDim.x + threadIdx.x;
    int total = N * 16;
    if (i >= total) return;
    int node = i >> 4;
    int c = i & 15;
    const float4* p = (node < U)
        ? (const float4*)ue + (size_t)node * 16
        : (const float4*)ie + (size_t)(node - U) * 16;
    g_h0[i] = f4_to_h4(__ldg(p + c));
}

// ---------------------------------------------------------------------------
// Fused layer: 16 threads per node (half-warp), thread c owns halves [4c,4c+4).
// User rows: adjacency = input col stream, weight = d*dinv[col] (table).
// Item rows: adjacency = int2 {col, weight} inline.
template<bool LAST>
__global__ void __launch_bounds__(TB)
k_layer(const uint2* __restrict__ x,
        uint2* __restrict__ xn,
        const int* __restrict__ gcol,
        const float* __restrict__ ue,
        const float* __restrict__ ie,
        int U,
        float* __restrict__ acc,
        int N) {
    int t = blockIdx.x * blockDim.x + threadIdx.x;
    int node = t >> 4;
    if (node >= N) return;
    int c = t & 15;

    float d = __ldg(&g_dinv[node]);
    int2 rng = __ldg(&g_rng[node]);
    int e = rng.x, end = rng.y;

    size_t idx = (size_t)node * 16 + c;
    float4 xs = h4_to_f4(__ldg(x + idx));
    float sw = d * d;
    float4 s0 = make_float4(sw * xs.x, sw * xs.y, sw * xs.z, sw * xs.w);
    float4 s1 = make_float4(0.f, 0.f, 0.f, 0.f);

    if (node < U) {
        while (e + 4 <= end) {
            int c0 = __ldg(gcol + e);
            int c1 = __ldg(gcol + e + 1);
            int c2 = __ldg(gcol + e + 2);
            int c3 = __ldg(gcol + e + 3);
            float4 v0 = h4_to_f4(__ldg(x + (size_t)c0 * 16 + c));
            float4 v1 = h4_to_f4(__ldg(x + (size_t)c1 * 16 + c));
            float4 v2 = h4_to_f4(__ldg(x + (size_t)c2 * 16 + c));
            float4 v3 = h4_to_f4(__ldg(x + (size_t)c3 * 16 + c));
            float w0 = d * __ldg(&g_dinv[c0]);
            float w1 = d * __ldg(&g_dinv[c1]);
            float w2 = d * __ldg(&g_dinv[c2]);
            float w3 = d * __ldg(&g_dinv[c3]);
            s0.x += w0 * v0.x + w2 * v2.x;  s1.x += w1 * v1.x + w3 * v3.x;
            s0.y += w0 * v0.y + w2 * v2.y;  s1.y += w1 * v1.y + w3 * v3.y;
            s0.z += w0 * v0.z + w2 * v2.z;  s1.z += w1 * v1.z + w3 * v3.z;
            s0.w += w0 * v0.w + w2 * v2.w;  s1.w += w1 * v1.w + w3 * v3.w;
            e += 4;
        }
        if (e + 2 <= end) {
            int c0 = __ldg(gcol + e);
            int c1 = __ldg(gcol + e + 1);
            float4 v0 = h4_to_f4(__ldg(x + (size_t)c0 * 16 + c));
            float4 v1 = h4_to_f4(__ldg(x + (size_t)c1 * 16 + c));
            float w0 = d * __ldg(&g_dinv[c0]);
            float w1 = d * __ldg(&g_dinv[c1]);
            s0.x += w0 * v0.x; s0.y += w0 * v0.y; s0.z += w0 * v0.z; s0.w += w0 * v0.w;
            s1.x += w1 * v1.x; s1.y += w1 * v1.y; s1.z += w1 * v1.z; s1.w += w1 * v1.w;
            e += 2;
        }
        if (e < end) {
            int c0 = __ldg(gcol + e);
            float4 v0 = h4_to_f4(__ldg(x + (size_t)c0 * 16 + c));
            float w0 = d * __ldg(&g_dinv[c0]);
            s0.x += w0 * v0.x; s0.y += w0 * v0.y; s0.z += w0 * v0.z; s0.w += w0 * v0.w;
        }
    } else {
        while (e + 4 <= end) {
            int2 a0 = __ldg(&g_adji[e]);
            int2 a1 = __ldg(&g_adji[e + 1]);
            int2 a2 = __ldg(&g_adji[e + 2]);
            int2 a3 = __ldg(&g_adji[e + 3]);
            float4 v0 = h4_to_f4(__ldg(x + (size_t)a0.x * 16 + c));
            float4 v1 = h4_to_f4(__ldg(x + (size_t)a1.x * 16 + c));
            float4 v2 = h4_to_f4(__ldg(x + (size_t)a2.x * 16 + c));
            float4 v3 = h4_to_f4(__ldg(x + (size_t)a3.x * 16 + c));
            float w0 = d * __int_as_float(a0.y);
            float w1 = d * __int_as_float(a1.y);
            float w2 = d * __int_as_float(a2.y);
            float w3 = d * __int_as_float(a3.y);
            s0.x += w0 * v0.x + w2 * v2.x;  s1.x += w1 * v1.x + w3 * v3.x;
            s0.y += w0 * v0.y + w2 * v2.y;  s1.y += w1 * v1.y + w3 * v3.y;
            s0.z += w0 * v0.z + w2 * v2.z;  s1.z += w1 * v1.z + w3 * v3.z;
            s0.w += w0 * v0.w + w2 * v2.w;  s1.w += w1 * v1.w + w3 * v3.w;
            e += 4;
        }
        if (e + 2 <= end) {
            int2 a0 = __ldg(&g_adji[e]);
            int2 a1 = __ldg(&g_adji[e + 1]);
            float4 v0 = h4_to_f4(__ldg(x + (size_t)a0.x * 16 + c));
            float4 v1 = h4_to_f4(__ldg(x + (size_t)a1.x * 16 + c));
            float w0 = d * __int_as_float(a0.y);
            float w1 = d * __int_as_float(a1.y);
            s0.x += w0 * v0.x; s0.y += w0 * v0.y; s0.z += w0 * v0.z; s0.w += w0 * v0.w;
            s1.x += w1 * v1.x; s1.y += w1 * v1.y; s1.z += w1 * v1.z; s1.w += w1 * v1.w;
            e += 2;
        }
        if (e < end) {
            int2 a0 = __ldg(&g_adji[e]);
            float4 v0 = h4_to_f4(__ldg(x + (size_t)a0.x * 16 + c));
            float w0 = d * __int_as_float(a0.y);
            s0.x += w0 * v0.x; s0.y += w0 * v0.y; s0.z += w0 * v0.z; s0.w += w0 * v0.w;
        }
    }
    float4 s = make_float4(s0.x + s1.x, s0.y + s1.y, s0.z + s1.z, s0.w + s1.w);

    if (!LAST) {
        xn[idx] = f4_to_h4(s);
    } else {
        const float4* pe = (node < U)
            ? (const float4*)ue + (size_t)node * 16
            : (const float4*)ie + (size_t)(node - U) * 16;
        float4 a  = __ldg(pe + c);
        float4 v1 = h4_to_f4(__ldg(&g_h1[idx]));
        a.x += v1.x + xs.x + s.x;
        a.y += v1.y + xs.y + s.y;
        a.z += v1.z + xs.z + s.z;
        a.w += v1.w + xs.w + s.w;
        __stcs((float4*)acc + idx, a);   // write-once output: evict-first
    }
}

// ---------------------------------------------------------------------------
extern "C" void kernel_launch(void* const* d_in, const int* in_sizes, int n_in,
                              void* d_out, int out_size) {
    const int*   edge = (const int*)d_in[0];
    const float* uemb = (const float*)d_in[1];
    const float* iemb = (const float*)d_in[2];

    int E = in_sizes[0] / 2;       // total directed edges
    int Eh = E / 2;                // unique interactions (mirrored halves)
    int U = in_sizes[1] / EMB;
    int I = in_sizes[2] / EMB;
    int N = U + I;

    const int* row = edge;         // first Eh: user ids (sorted ascending)
    const int* col = edge + E;     // first Eh: item ids (grouped per user)
    float* acc = (float*)d_out;

    uint2* h0; cudaGetSymbolAddress((void**)&h0, g_h0);
    uint2* h1; cudaGetSymbolAddress((void**)&h1, g_h1);
    uint2* h2; cudaGetSymbolAddress((void**)&h2, g_h2);

    int NB  = (N + TB - 1) / TB;
    int EBh = (Eh + TB - 1) / TB;
    int pblocks = (N * 16 + TB - 1) / TB;
    int lblocks = (N * 16 + TB - 1) / TB;

    // fork: run k_prep (emb->fp16, independent of the graph build) on a side
    // stream so the captured graph executes it concurrently with the build.
    cudaStream_t s2;
    cudaStreamCreateWithFlags(&s2, cudaStreamNonBlocking);
    cudaEvent_t evFork, evJoin;
    cudaEventCreateWithFlags(&evFork, cudaEventDisableTiming);
    cudaEventCreateWithFlags(&evJoin, cudaEventDisableTiming);

    cudaEventRecord(evFork, 0);
    cudaStreamWaitEvent(s2, evFork, 0);
    k_prep<<<pblocks, TB, 0, s2>>>(uemb, iemb, U, N);
    cudaEventRecord(evJoin, s2);

    // build chain on the main (capture) stream
    k_zero_deg  <<<NB, TB>>>(N);
    k_count_sym <<<EBh, TB>>>(row, col, Eh);
    k_scan_local<<<NB, TB>>>(N);
    k_scan_bsum <<<1, 1024>>>(NB);
    k_scan_add  <<<NB, TB>>>(N, U, Eh);
    k_fill_item <<<EBh, TB>>>(row, col, Eh);

    // join: layers need both the adjacency (main stream) and x0 (s2)
    cudaStreamWaitEvent(0, evJoin, 0);

    k_layer<false><<<lblocks, TB>>>(h0, h1, col, uemb, iemb, U, acc, N);
    k_layer<false><<<lblocks, TB>>>(h1, h2, col, uemb, iemb, U, acc, N);
    k_layer<true ><<<lblocks, TB>>>(h2, nullptr, col, uemb, iemb, U, acc, N);

    cudaEventDestroy(evFork);
    cudaEventDestroy(evJoin);
    cudaStreamDestroy(s2);
}